// round 9
// baseline (speedup 1.0000x reference)
#include <cuda_runtime.h>
#include <cstdint>

#define H 512
#define W 512
#define HW (H*W)
#define NB 2
#define NC 21
#define NPIX (NB*HW)
#define NTAP 25

// ping-pong q buffers + combined coefficient field, all fp32
__device__ float g_qA[NB*NC*HW];
__device__ float g_qB[NB*NC*HW];
__device__ float g_wc[NTAP*NB*HW];   // SoA: [tap][b][y][x]

__device__ __forceinline__ int reflect_idx(int i, int n) {
    if (i < 0) i = -i;
    if (i >= n) i = 2*n - 2 - i;
    return i;
}

// packed fp32x2 helpers (FFMA2 — PTX-only pattern on sm_103a)
__device__ __forceinline__ unsigned long long pk2(float lo, float hi) {
    unsigned long long r;
    asm("mov.b64 %0, {%1, %2};" : "=l"(r) : "f"(lo), "f"(hi));
    return r;
}
__device__ __forceinline__ void upk2(float& lo, float& hi, unsigned long long v) {
    asm("mov.b64 {%0, %1}, %2;" : "=f"(lo), "=f"(hi) : "l"(v));
}
#define FMA2(acc, a, b) \
    asm("fma.rn.f32x2 %0, %1, %2, %0;" : "+l"(acc) : "l"(a), "l"(b))

// ---------------------------------------------------------------------------
// Kernel 1: q0 = softmax(unary)
// ---------------------------------------------------------------------------
__global__ void __launch_bounds__(256) init_softmax(const float* __restrict__ unary,
                                                    float* __restrict__ q) {
    int idx = blockIdx.x * 256 + threadIdx.x;
    if (idx >= NPIX) return;
    int b = idx / HW, pix = idx % HW;
    const float* u = unary + (size_t)b * NC * HW + pix;
    float e[NC];
    float s = 0.f;
#pragma unroll
    for (int c = 0; c < NC; c++) { e[c] = __expf(u[c*HW]); s += e[c]; }
    float inv = 1.f / s;
    float* qo = q + (size_t)b * NC * HW + pix;
#pragma unroll
    for (int c = 0; c < NC; c++) qo[c*HW] = e[c] * inv;
}

// ---------------------------------------------------------------------------
// Kernel 2: combined coefficients (fp32)
//   Wc[t] = g2d[t] + w_rgb[t]/sum(w_rgb) + w_edge[t]/sum(w_edge)
// ---------------------------------------------------------------------------
__global__ void __launch_bounds__(256) compute_weights(const float* __restrict__ image,
                                                       const float* __restrict__ edges) {
    __shared__ float sg[4][12][36];   // rgb + edge, tile 32x8 + halo 2
    int tx = threadIdx.x, ty = threadIdx.y;
    int b = blockIdx.z;
    int x0 = blockIdx.x * 32, y0 = blockIdx.y * 8;
    int tid = ty * 32 + tx;

    for (int idx = tid; idx < 4*12*36; idx += 256) {
        int ch = idx / (12*36);
        int r  = idx % (12*36);
        int ry = r / 36, sx = r % 36;
        int gy = reflect_idx(y0 + ry - 2, H);
        int gx = reflect_idx(x0 + sx - 2, W);
        float v;
        if (ch < 3) v = image[((size_t)(b*3 + ch))*HW + gy*W + gx];
        else        v = edges[(size_t)b*HW + gy*W + gx];
        sg[ch][ry][sx] = v;
    }
    __syncthreads();

    float sp[5], g2[5];
    {
        float s = 0.f;
#pragma unroll
        for (int i = 0; i < 5; i++) {
            float x = (float)(i - 2);
            sp[i] = __expf(-x*x * 0.02f);    // spatial, sigma_space=5 (norm cancels)
            float g = __expf(-2.f * x*x);    // blur kernel, sigma=0.5
            g2[i] = g; s += g;
        }
        float inv = 1.f / s;
#pragma unroll
        for (int i = 0; i < 5; i++) g2[i] *= inv;
    }

    int ry = ty + 2, rx = tx + 2;
    float cr = sg[0][ry][rx], cg = sg[1][ry][rx], cb = sg[2][ry][rx], ce = sg[3][ry][rx];

    float wr[NTAP], we[NTAP];
    float sr = 0.f, se = 0.f;
#pragma unroll
    for (int dy = 0; dy < 5; dy++) {
#pragma unroll
        for (int dx = 0; dx < 5; dx++) {
            int t = dy*5 + dx;
            float d = fabsf(sg[0][ry+dy-2][rx+dx-2] - cr)
                    + fabsf(sg[1][ry+dy-2][rx+dx-2] - cg)
                    + fabsf(sg[2][ry+dy-2][rx+dx-2] - cb);
            float s2 = sp[dy] * sp[dx];
            float w  = s2 * __expf(-2.f * d * d);
            wr[t] = w; sr += w;
            float de = fabsf(sg[3][ry+dy-2][rx+dx-2] - ce);
            float w2 = s2 * __expf(-2.f * de * de);
            we[t] = w2; se += w2;
        }
    }
    float isr = 1.f / sr, ise = 1.f / se;
    int pix = b*HW + (y0 + ty)*W + (x0 + tx);
#pragma unroll
    for (int dy = 0; dy < 5; dy++) {
#pragma unroll
        for (int dx = 0; dx < 5; dx++) {
            int t = dy*5 + dx;
            g_wc[t*(NB*HW) + pix] = g2[dy]*g2[dx] + wr[t]*isr + we[t]*ise;
        }
    }
}

// ---------------------------------------------------------------------------
// Kernel 3: one CRF iteration.
// Block (16,8)=128 thr, tile 64x8, 4 px/thread in x, 3 CTAs/SM.
// smem [NC][SH][SW=72] fp32 with XOR swizzle (xoff ^= (xoff>>4)&8) to make
// the 16B-stride window LDS.64s bank-conflict-free. Fill via paired 8B
// cp.async (halves swapped when swizzle bit set). Stencil = packed FFMA2.
// ---------------------------------------------------------------------------
#define TX 64
#define TY 8
#define SW 72            // covers x0-4 .. x0+67
#define SH 12            // TY + 4
#define ROWB (SW*4)      // 288 B per row
#define CHB  (SH*ROWB)   // 3456 B per channel plane
#define NCH16 (NC*SH*18) // 16B chunks: 4536
#define NCH8  (NC*SH*36) // 8B  chunks: 9072

__global__ void __launch_bounds__(128, 3) crf_iter(const float* __restrict__ unary,
                                                   const float* __restrict__ qin,
                                                   float* __restrict__ qout) {
    __shared__ float sq[NC*SH*SW];
    int tx = threadIdx.x;            // 0..15
    int ty = threadIdx.y;            // 0..7
    int b = blockIdx.z;
    int x0 = blockIdx.x * TX, y0 = blockIdx.y * TY;
    int tid = ty * 16 + tx;

    const float* qb = qin + (size_t)b * NC * HW;
    uint32_t sbase = (uint32_t)__cvta_generic_to_shared(sq);

    bool xInt = (blockIdx.x != 0) && (blockIdx.x != (int)gridDim.x - 1);

    if (xInt) {
        // 16B chunk = 2x 8B cp.async with conditional half-swap (swizzle)
        int cx = tid % 18;           // 16B-chunk column (0..17)
        int row0 = tid / 18;
        int ry = row0 % SH, c = row0 / SH;
#pragma unroll
        for (int it = 0; it < 36; it++) {
            int idx = tid + it*128;
            if (idx < NCH16) {
                int gy = reflect_idx(y0 + ry - 2, H);
                const float* src = qb + c*HW + gy*W + (x0 - 4) + cx*4;
                uint32_t d  = sbase + (uint32_t)(c*CHB + ry*ROWB + cx*16);
                uint32_t bb = (uint32_t)(cx & 8);
                asm volatile("cp.async.ca.shared.global [%0], [%1], 8;"
                             :: "r"(d + bb), "l"(src));
                asm volatile("cp.async.ca.shared.global [%0], [%1], 8;"
                             :: "r"(d + (bb ^ 8u)), "l"(src + 2));
            }
            cx += 2; if (cx >= 18) { cx -= 18; ry++; }
            ry += 7; if (ry >= SH) { ry -= SH; c++; }
        }
        asm volatile("cp.async.commit_group;");
        asm volatile("cp.async.wait_group 0;" ::: "memory");
    } else {
        // boundary blocks: scalar reflect path, 8B granularity
        int cx = tid % 36;           // 8B-chunk column (0..35)
        int row0 = tid / 36;
        int ry = row0 % SH, c = row0 / SH;
        for (int it = 0; it < 71; it++) {
            int idx = tid + it*128;
            if (idx < NCH8) {
                int gy = reflect_idx(y0 + ry - 2, H);
                const float* src = qb + c*HW + gy*W;
                float2 v;
                v.x = src[reflect_idx(x0 - 4 + cx*2,     W)];
                v.y = src[reflect_idx(x0 - 4 + cx*2 + 1, W)];
                uint32_t xo = (uint32_t)(cx*8);
                xo ^= ((xo >> 4) & 8u);
                *reinterpret_cast<float2*>(
                    reinterpret_cast<char*>(sq) + c*CHB + ry*ROWB + xo) = v;
            }
            cx += 20; int rinc = 3; if (cx >= 36) { cx -= 36; rinc = 4; }
            ry += rinc; if (ry >= SH) { ry -= SH; c++; }
        }
    }
    __syncthreads();

    int gx0 = x0 + tx*4;
    int gy  = y0 + ty;

    // per-thread constant swizzled window offsets (bytes within a row)
    uint32_t xsw0, xsw1, xsw2, xsw3;
    {
        uint32_t xo0 = (uint32_t)(16*tx + 8);
        xsw0 = xo0        ^ (((xo0       ) >> 4) & 8u);
        xsw1 = (xo0 + 8)  ^ (((xo0 + 8 ) >> 4) & 8u);
        xsw2 = (xo0 + 16) ^ (((xo0 + 16) >> 4) & 8u);
        xsw3 = (xo0 + 24) ^ (((xo0 + 24) >> 4) & 8u);
    }

    unsigned long long accL[NC], accR[NC];
#pragma unroll
    for (int cc = 0; cc < NC; cc++) { accL[cc] = 0ULL; accR[cc] = 0ULL; }

    int wbase = b*HW + gy*W + gx0;
#pragma unroll 1
    for (int dy = 0; dy < 5; dy++) {
        // coef float4 per tap: (c[p0],c[p1],c[p2],c[p3]) — LDG.128
        const float* wp = g_wc + (size_t)(dy*5)*(NB*HW) + wbase;
        float4 cf0 = *reinterpret_cast<const float4*>(wp);
        float4 cf1 = *reinterpret_cast<const float4*>(wp +   (size_t)NB*HW);
        float4 cf2 = *reinterpret_cast<const float4*>(wp + 2*(size_t)NB*HW);
        float4 cf3 = *reinterpret_cast<const float4*>(wp + 3*(size_t)NB*HW);
        float4 cf4 = *reinterpret_cast<const float4*>(wp + 4*(size_t)NB*HW);
        unsigned long long CL0 = pk2(cf0.x, cf0.y), CR0 = pk2(cf0.z, cf0.w);
        unsigned long long CL1 = pk2(cf1.x, cf1.y), CR1 = pk2(cf1.z, cf1.w);
        unsigned long long CL2 = pk2(cf2.x, cf2.y), CR2 = pk2(cf2.z, cf2.w);
        unsigned long long CL3 = pk2(cf3.x, cf3.y), CR3 = pk2(cf3.z, cf3.w);
        unsigned long long CL4 = pk2(cf4.x, cf4.y), CR4 = pk2(cf4.z, cf4.w);

        const char* rp0 = reinterpret_cast<const char*>(sq) + (ty + dy)*ROWB;
#pragma unroll
        for (int ch = 0; ch < NC; ch++) {
            const char* rp = rp0 + ch*CHB;
            float2 A0 = *reinterpret_cast<const float2*>(rp + xsw0); // w0 w1
            float2 A1 = *reinterpret_cast<const float2*>(rp + xsw1); // w2 w3
            float2 A2 = *reinterpret_cast<const float2*>(rp + xsw2); // w4 w5
            float2 A3 = *reinterpret_cast<const float2*>(rp + xsw3); // w6 w7
            unsigned long long a0 = pk2(A0.x, A0.y);
            unsigned long long a1 = pk2(A1.x, A1.y);
            unsigned long long a2 = pk2(A2.x, A2.y);
            unsigned long long a3 = pk2(A3.x, A3.y);
            unsigned long long b0 = pk2(A0.y, A1.x);  // w1 w2
            unsigned long long b1 = pk2(A1.y, A2.x);  // w3 w4
            unsigned long long b2 = pk2(A2.y, A3.x);  // w5 w6
            FMA2(accL[ch], CL0, a0);
            FMA2(accL[ch], CL1, b0);
            FMA2(accL[ch], CL2, a1);
            FMA2(accL[ch], CL3, b1);
            FMA2(accL[ch], CL4, a2);
            FMA2(accR[ch], CR0, a1);
            FMA2(accR[ch], CR1, b1);
            FMA2(accR[ch], CR2, a2);
            FMA2(accR[ch], CR3, b2);
            FMA2(accR[ch], CR4, a3);
        }
    }

    // q_out = softmax(unary - F); exp results packed back into acc (reg reuse)
    const float* ub = unary + (size_t)b * NC * HW + gy*W + gx0;
    float s0 = 0.f, s1 = 0.f, s2 = 0.f, s3 = 0.f;
#pragma unroll
    for (int ch = 0; ch < NC; ch++) {
        float4 u = *reinterpret_cast<const float4*>(ub + (size_t)ch*HW);
        float f0, f1, f2, f3;
        upk2(f0, f1, accL[ch]);
        upk2(f2, f3, accR[ch]);
        float e0 = __expf(u.x - f0);
        float e1 = __expf(u.y - f1);
        float e2 = __expf(u.z - f2);
        float e3 = __expf(u.w - f3);
        accL[ch] = pk2(e0, e1);
        accR[ch] = pk2(e2, e3);
        s0 += e0; s1 += e1; s2 += e2; s3 += e3;
    }
    float i0 = 1.f / s0, i1 = 1.f / s1, i2 = 1.f / s2, i3 = 1.f / s3;
    float* qo = qout + (size_t)b * NC * HW + gy*W + gx0;
#pragma unroll
    for (int ch = 0; ch < NC; ch++) {
        float e0, e1, e2, e3;
        upk2(e0, e1, accL[ch]);
        upk2(e2, e3, accR[ch]);
        float4 o; o.x = e0*i0; o.y = e1*i1; o.z = e2*i2; o.w = e3*i3;
        *reinterpret_cast<float4*>(qo + (size_t)ch*HW) = o;
    }
}

// ---------------------------------------------------------------------------
extern "C" void kernel_launch(void* const* d_in, const int* in_sizes, int n_in,
                              void* d_out, int out_size) {
    const float *unary = nullptr, *image = nullptr, *edges = nullptr;
    for (int i = 0; i < n_in; i++) {
        if      (in_sizes[i] == NB*NC*HW) unary = (const float*)d_in[i];
        else if (in_sizes[i] == NB*3*HW)  image = (const float*)d_in[i];
        else if (in_sizes[i] == NB*HW)    edges = (const float*)d_in[i];
    }
    float* out = (float*)d_out;

    float *qA = nullptr, *qB = nullptr;
    cudaGetSymbolAddress((void**)&qA, g_qA);
    cudaGetSymbolAddress((void**)&qB, g_qB);

    init_softmax<<<(NPIX + 255)/256, 256>>>(unary, qA);
    compute_weights<<<dim3(W/32, H/8, NB), dim3(32, 8)>>>(image, edges);

    dim3 gi(W/TX, H/TY, NB), bi(16, 8);
    const float* cur = qA;
    for (int it = 0; it < 10; it++) {
        float* dst = (it == 9) ? out : ((cur == qA) ? qB : qA);
        crf_iter<<<gi, bi>>>(unary, cur, dst);
        cur = dst;
    }
}

// round 10
// speedup vs baseline: 1.5792x; 1.5792x over previous
#include <cuda_runtime.h>
#include <cstdint>

#define H 512
#define W 512
#define HW (H*W)
#define NB 2
#define NC 21
#define NPIX (NB*HW)
#define NTAP 25

// ping-pong q buffers + combined coefficient field, all fp32
__device__ float g_qA[NB*NC*HW];
__device__ float g_qB[NB*NC*HW];
__device__ float g_wc[NTAP*NB*HW];   // SoA: [tap][b][y][x]

__device__ __forceinline__ int reflect_idx(int i, int n) {
    if (i < 0) i = -i;
    if (i >= n) i = 2*n - 2 - i;
    return i;
}

// packed fp32x2 helpers (FFMA2 — PTX-only pattern on sm_103a)
__device__ __forceinline__ unsigned long long pk2(float lo, float hi) {
    unsigned long long r;
    asm("mov.b64 %0, {%1, %2};" : "=l"(r) : "f"(lo), "f"(hi));
    return r;
}
__device__ __forceinline__ void upk2(float& lo, float& hi, unsigned long long v) {
    asm("mov.b64 {%0, %1}, %2;" : "=f"(lo), "=f"(hi) : "l"(v));
}
#define FMA2(acc, a, b) \
    asm("fma.rn.f32x2 %0, %1, %2, %0;" : "+l"(acc) : "l"(a), "l"(b))

// ---------------------------------------------------------------------------
// Kernel 1: q0 = softmax(unary)
// ---------------------------------------------------------------------------
__global__ void __launch_bounds__(256) init_softmax(const float* __restrict__ unary,
                                                    float* __restrict__ q) {
    int idx = blockIdx.x * 256 + threadIdx.x;
    if (idx >= NPIX) return;
    int b = idx / HW, pix = idx % HW;
    const float* u = unary + (size_t)b * NC * HW + pix;
    float e[NC];
    float s = 0.f;
#pragma unroll
    for (int c = 0; c < NC; c++) { e[c] = __expf(u[c*HW]); s += e[c]; }
    float inv = 1.f / s;
    float* qo = q + (size_t)b * NC * HW + pix;
#pragma unroll
    for (int c = 0; c < NC; c++) qo[c*HW] = e[c] * inv;
}

// ---------------------------------------------------------------------------
// Kernel 2: combined coefficients (fp32)
//   Wc[t] = g2d[t] + w_rgb[t]/sum(w_rgb) + w_edge[t]/sum(w_edge)
// ---------------------------------------------------------------------------
__global__ void __launch_bounds__(256) compute_weights(const float* __restrict__ image,
                                                       const float* __restrict__ edges) {
    __shared__ float sg[4][12][36];   // rgb + edge, tile 32x8 + halo 2
    int tx = threadIdx.x, ty = threadIdx.y;
    int b = blockIdx.z;
    int x0 = blockIdx.x * 32, y0 = blockIdx.y * 8;
    int tid = ty * 32 + tx;

    for (int idx = tid; idx < 4*12*36; idx += 256) {
        int ch = idx / (12*36);
        int r  = idx % (12*36);
        int ry = r / 36, sx = r % 36;
        int gy = reflect_idx(y0 + ry - 2, H);
        int gx = reflect_idx(x0 + sx - 2, W);
        float v;
        if (ch < 3) v = image[((size_t)(b*3 + ch))*HW + gy*W + gx];
        else        v = edges[(size_t)b*HW + gy*W + gx];
        sg[ch][ry][sx] = v;
    }
    __syncthreads();

    float sp[5], g2[5];
    {
        float s = 0.f;
#pragma unroll
        for (int i = 0; i < 5; i++) {
            float x = (float)(i - 2);
            sp[i] = __expf(-x*x * 0.02f);    // spatial, sigma_space=5 (norm cancels)
            float g = __expf(-2.f * x*x);    // blur kernel, sigma=0.5
            g2[i] = g; s += g;
        }
        float inv = 1.f / s;
#pragma unroll
        for (int i = 0; i < 5; i++) g2[i] *= inv;
    }

    int ry = ty + 2, rx = tx + 2;
    float cr = sg[0][ry][rx], cg = sg[1][ry][rx], cb = sg[2][ry][rx], ce = sg[3][ry][rx];

    float wr[NTAP], we[NTAP];
    float sr = 0.f, se = 0.f;
#pragma unroll
    for (int dy = 0; dy < 5; dy++) {
#pragma unroll
        for (int dx = 0; dx < 5; dx++) {
            int t = dy*5 + dx;
            float d = fabsf(sg[0][ry+dy-2][rx+dx-2] - cr)
                    + fabsf(sg[1][ry+dy-2][rx+dx-2] - cg)
                    + fabsf(sg[2][ry+dy-2][rx+dx-2] - cb);
            float s2 = sp[dy] * sp[dx];
            float w  = s2 * __expf(-2.f * d * d);
            wr[t] = w; sr += w;
            float de = fabsf(sg[3][ry+dy-2][rx+dx-2] - ce);
            float w2 = s2 * __expf(-2.f * de * de);
            we[t] = w2; se += w2;
        }
    }
    float isr = 1.f / sr, ise = 1.f / se;
    int pix = b*HW + (y0 + ty)*W + (x0 + tx);
#pragma unroll
    for (int dy = 0; dy < 5; dy++) {
#pragma unroll
        for (int dx = 0; dx < 5; dx++) {
            int t = dy*5 + dx;
            g_wc[t*(NB*HW) + pix] = g2[dy]*g2[dx] + wr[t]*isr + we[t]*ise;
        }
    }
}

// ---------------------------------------------------------------------------
// Kernel 3: one CRF iteration.
// Tile 64x8, block (32,8)=256 thr, 2 px/thread, 3 CTAs/SM (regs<=85).
// Two-stage channel-group pipeline: cp.async group A (ch 0..10) + group B
// (ch 11..20) issued back-to-back; compute A overlaps group B's DRAM traffic.
// Stencil = packed FFMA2.
// ---------------------------------------------------------------------------
#define TX 64
#define TY 8
#define SW 72            // x0-4 .. x0+67
#define SH 12            // TY + 4
#define ROWB (SW*4)      // 288 bytes per smem row
#define NCA 11           // channels in group A
#define NCB 10           // channels in group B
#define CHKA (NCA*SH*18) // 16B chunks group A: 2376
#define CHKB (NCB*SH*18) // 16B chunks group B: 2160
#define NCHUNK (NC*SH*18)

__global__ void __launch_bounds__(256, 3) crf_iter(const float* __restrict__ unary,
                                                   const float* __restrict__ qin,
                                                   float* __restrict__ qout) {
    __shared__ float sq[NC*SH*SW];
    int tx = threadIdx.x, ty = threadIdx.y;
    int b = blockIdx.z;
    int x0 = blockIdx.x * TX, y0 = blockIdx.y * TY;
    int tid = ty * 32 + tx;

    const float* qb = qin + (size_t)b * NC * HW;
    uint32_t sbase = (uint32_t)__cvta_generic_to_shared(sq);

    bool xInt = (blockIdx.x != 0) && (blockIdx.x != (int)gridDim.x - 1);

    if (xInt) {
        // group A: channels 0..10
#pragma unroll
        for (int it = 0; it < 10; it++) {
            int idx = tid + it*256;
            if (idx < CHKA) {
                int cx  = idx % 18;
                int row = idx / 18;
                int ry  = row % SH;
                int c   = row / SH;
                int gy  = reflect_idx(y0 + ry - 2, H);
                const float* src = qb + c*HW + gy*W + (x0 - 4 + cx*4);
                uint32_t dst = sbase + (uint32_t)(row*ROWB + cx*16);
                asm volatile("cp.async.cg.shared.global [%0], [%1], 16;"
                             :: "r"(dst), "l"(src));
            }
        }
        asm volatile("cp.async.commit_group;");
        // group B: channels 11..20
#pragma unroll
        for (int it = 0; it < 9; it++) {
            int idx = tid + it*256;
            if (idx < CHKB) {
                int cx  = idx % 18;
                int row = idx / 18;
                int ry  = row % SH;
                int c   = NCA + row / SH;
                int gy  = reflect_idx(y0 + ry - 2, H);
                const float* src = qb + c*HW + gy*W + (x0 - 4 + cx*4);
                uint32_t dst = sbase + (uint32_t)((row + NCA*SH)*ROWB + cx*16);
                asm volatile("cp.async.cg.shared.global [%0], [%1], 16;"
                             :: "r"(dst), "l"(src));
            }
        }
        asm volatile("cp.async.commit_group;");
    } else {
        // boundary blocks: scalar reflect path for all channels
#pragma unroll 3
        for (int it = 0; it < 18; it++) {
            int idx = tid + it*256;
            if (idx < NCHUNK) {
                int cx  = idx % 18;
                int row = idx / 18;
                int ry  = row % SH;
                int c   = row / SH;
                int gy  = reflect_idx(y0 + ry - 2, H);
                const float* src = qb + c*HW + gy*W;
                float4 v;
                v.x = src[reflect_idx(x0 - 4 + cx*4,     W)];
                v.y = src[reflect_idx(x0 - 4 + cx*4 + 1, W)];
                v.z = src[reflect_idx(x0 - 4 + cx*4 + 2, W)];
                v.w = src[reflect_idx(x0 - 4 + cx*4 + 3, W)];
                *reinterpret_cast<float4*>(
                    reinterpret_cast<char*>(sq) + row*ROWB + cx*16) = v;
            }
        }
    }

    int xl  = tx * 2;
    int gx0 = x0 + xl;
    int gy  = y0 + ty;
    int wbase = b*HW + gy*W + gx0;

    unsigned long long acc[NC];
#pragma unroll
    for (int cc = 0; cc < NC; cc++) acc[cc] = 0ULL;

    // ---- stage A: wait group A only (group B still in flight) ----
    if (xInt) asm volatile("cp.async.wait_group 1;" ::: "memory");
    __syncthreads();

#pragma unroll
    for (int dy = 0; dy < 5; dy++) {
        unsigned long long C0, C1, C2, C3, C4;
        {
            const float* wp = g_wc + (size_t)(dy*5)*(NB*HW) + wbase;
            C0 = *reinterpret_cast<const unsigned long long*>(wp);
            C1 = *reinterpret_cast<const unsigned long long*>(wp + NB*HW);
            C2 = *reinterpret_cast<const unsigned long long*>(wp + 2*NB*HW);
            C3 = *reinterpret_cast<const unsigned long long*>(wp + 3*NB*HW);
            C4 = *reinterpret_cast<const unsigned long long*>(wp + 4*NB*HW);
        }
        const float* rowb = sq + (ty + dy)*SW + xl + 2;
#pragma unroll
        for (int ch = 0; ch < NCA; ch++) {
            const float* rp = rowb + ch*(SH*SW);
            float2 a0 = *reinterpret_cast<const float2*>(rp);
            float2 a1 = *reinterpret_cast<const float2*>(rp + 2);
            float2 a2 = *reinterpret_cast<const float2*>(rp + 4);
            unsigned long long A0 = pk2(a0.x, a0.y);
            unsigned long long B0 = pk2(a0.y, a1.x);
            unsigned long long A1 = pk2(a1.x, a1.y);
            unsigned long long B1 = pk2(a1.y, a2.x);
            unsigned long long A2 = pk2(a2.x, a2.y);
            FMA2(acc[ch], C0, A0);
            FMA2(acc[ch], C1, B0);
            FMA2(acc[ch], C2, A1);
            FMA2(acc[ch], C3, B1);
            FMA2(acc[ch], C4, A2);
        }
    }

    // ---- stage B: wait group B ----
    if (xInt) asm volatile("cp.async.wait_group 0;" ::: "memory");
    __syncthreads();

#pragma unroll
    for (int dy = 0; dy < 5; dy++) {
        unsigned long long C0, C1, C2, C3, C4;
        {
            const float* wp = g_wc + (size_t)(dy*5)*(NB*HW) + wbase;
            C0 = *reinterpret_cast<const unsigned long long*>(wp);
            C1 = *reinterpret_cast<const unsigned long long*>(wp + NB*HW);
            C2 = *reinterpret_cast<const unsigned long long*>(wp + 2*NB*HW);
            C3 = *reinterpret_cast<const unsigned long long*>(wp + 3*NB*HW);
            C4 = *reinterpret_cast<const unsigned long long*>(wp + 4*NB*HW);
        }
        const float* rowb = sq + (ty + dy)*SW + xl + 2;
#pragma unroll
        for (int ch = NCA; ch < NC; ch++) {
            const float* rp = rowb + ch*(SH*SW);
            float2 a0 = *reinterpret_cast<const float2*>(rp);
            float2 a1 = *reinterpret_cast<const float2*>(rp + 2);
            float2 a2 = *reinterpret_cast<const float2*>(rp + 4);
            unsigned long long A0 = pk2(a0.x, a0.y);
            unsigned long long B0 = pk2(a0.y, a1.x);
            unsigned long long A1 = pk2(a1.x, a1.y);
            unsigned long long B1 = pk2(a1.y, a2.x);
            unsigned long long A2 = pk2(a2.x, a2.y);
            FMA2(acc[ch], C0, A0);
            FMA2(acc[ch], C1, B0);
            FMA2(acc[ch], C2, A1);
            FMA2(acc[ch], C3, B1);
            FMA2(acc[ch], C4, A2);
        }
    }

    // q_out = softmax(unary - F); exp results packed back into acc (reg reuse)
    const float* ub = unary + (size_t)b * NC * HW + gy*W + gx0;
    float s0 = 0.f, s1 = 0.f;
#pragma unroll
    for (int ch = 0; ch < NC; ch++) {
        float2 u = *reinterpret_cast<const float2*>(ub + ch*HW);
        float f0, f1;
        upk2(f0, f1, acc[ch]);
        float e0 = __expf(u.x - f0);
        float e1 = __expf(u.y - f1);
        acc[ch] = pk2(e0, e1);
        s0 += e0; s1 += e1;
    }
    float i0 = 1.f / s0, i1 = 1.f / s1;
    float* qo = qout + (size_t)b * NC * HW + gy*W + gx0;
#pragma unroll
    for (int ch = 0; ch < NC; ch++) {
        float e0, e1;
        upk2(e0, e1, acc[ch]);
        float2 o; o.x = e0*i0; o.y = e1*i1;
        *reinterpret_cast<float2*>(qo + ch*HW) = o;
    }
}

// ---------------------------------------------------------------------------
extern "C" void kernel_launch(void* const* d_in, const int* in_sizes, int n_in,
                              void* d_out, int out_size) {
    const float *unary = nullptr, *image = nullptr, *edges = nullptr;
    for (int i = 0; i < n_in; i++) {
        if      (in_sizes[i] == NB*NC*HW) unary = (const float*)d_in[i];
        else if (in_sizes[i] == NB*3*HW)  image = (const float*)d_in[i];
        else if (in_sizes[i] == NB*HW)    edges = (const float*)d_in[i];
    }
    float* out = (float*)d_out;

    float *qA = nullptr, *qB = nullptr;
    cudaGetSymbolAddress((void**)&qA, g_qA);
    cudaGetSymbolAddress((void**)&qB, g_qB);

    init_softmax<<<(NPIX + 255)/256, 256>>>(unary, qA);
    compute_weights<<<dim3(W/32, H/8, NB), dim3(32, 8)>>>(image, edges);

    dim3 gi(W/TX, H/TY, NB), bi(32, 8);
    const float* cur = qA;
    for (int it = 0; it < 10; it++) {
        float* dst = (it == 9) ? out : ((cur == qA) ? qB : qA);
        crf_iter<<<gi, bi>>>(unary, cur, dst);
        cur = dst;
    }
}

// round 11
// speedup vs baseline: 1.6406x; 1.0389x over previous
#include <cuda_runtime.h>
#include <cstdint>

#define H 512
#define W 512
#define HW (H*W)
#define NB 2
#define NC 21
#define NCC 11           // channel pairs (ch20 paired with zero pad)
#define NPIX (NB*HW)
#define NTAP 25
#define NBHW (NB*HW)

// q buffers: pair-planar layout [b][y][cc][x][2] fp32; coefs planar fp32
__device__ float g_qA[(size_t)NB*H*NCC*W*2];
__device__ float g_qB[(size_t)NB*H*NCC*W*2];
__device__ float g_wc[NTAP*NB*HW];

__device__ __forceinline__ int reflect_idx(int i, int n) {
    if (i < 0) i = -i;
    if (i >= n) i = 2*n - 2 - i;
    return i;
}

__device__ __forceinline__ unsigned long long pk2(float lo, float hi) {
    unsigned long long r;
    asm("mov.b64 %0, {%1, %2};" : "=l"(r) : "f"(lo), "f"(hi));
    return r;
}
__device__ __forceinline__ void upk2(float& lo, float& hi, unsigned long long v) {
    asm("mov.b64 {%0, %1}, %2;" : "=f"(lo), "=f"(hi) : "l"(v));
}
#define FMA2(acc, a, b) \
    asm("fma.rn.f32x2 %0, %1, %2, %0;" : "+l"(acc) : "l"(a), "l"(b))
#define MUL2(out, a, b) \
    asm("mul.rn.f32x2 %0, %1, %2;" : "=l"(out) : "l"(a), "l"(b))

// ---------------------------------------------------------------------------
// Kernel 1: q0 = softmax(unary), written pair-planar
// ---------------------------------------------------------------------------
__global__ void __launch_bounds__(256) init_softmax(const float* __restrict__ unary,
                                                    float* __restrict__ q) {
    int idx = blockIdx.x * 256 + threadIdx.x;
    if (idx >= NPIX) return;
    int b = idx / HW, pix = idx % HW;
    int y = pix / W, x = pix % W;
    const float* u = unary + (size_t)b * NC * HW + pix;
    float e[NC];
    float s = 0.f;
#pragma unroll
    for (int c = 0; c < NC; c++) { e[c] = __expf(u[c*HW]); s += e[c]; }
    float inv = 1.f / s;
    float* qr = q + ((size_t)(b*H + y)*NCC)*(W*2) + x*2;
#pragma unroll
    for (int cc = 0; cc < 10; cc++) {
        float2 v; v.x = e[2*cc]*inv; v.y = e[2*cc+1]*inv;
        *reinterpret_cast<float2*>(qr + cc*(W*2)) = v;
    }
    float2 v10; v10.x = e[20]*inv; v10.y = 0.f;
    *reinterpret_cast<float2*>(qr + 10*(W*2)) = v10;
}

// ---------------------------------------------------------------------------
// Kernel 2: combined coefficients (fp32, planar SoA [tap][b][y][x])
// ---------------------------------------------------------------------------
__global__ void __launch_bounds__(256) compute_weights(const float* __restrict__ image,
                                                       const float* __restrict__ edges) {
    __shared__ float sg[4][12][36];
    int tx = threadIdx.x, ty = threadIdx.y;
    int b = blockIdx.z;
    int x0 = blockIdx.x * 32, y0 = blockIdx.y * 8;
    int tid = ty * 32 + tx;

    for (int idx = tid; idx < 4*12*36; idx += 256) {
        int ch = idx / (12*36);
        int r  = idx % (12*36);
        int ry = r / 36, sx = r % 36;
        int gy = reflect_idx(y0 + ry - 2, H);
        int gx = reflect_idx(x0 + sx - 2, W);
        float v;
        if (ch < 3) v = image[((size_t)(b*3 + ch))*HW + gy*W + gx];
        else        v = edges[(size_t)b*HW + gy*W + gx];
        sg[ch][ry][sx] = v;
    }
    __syncthreads();

    float sp[5], g2[5];
    {
        float s = 0.f;
#pragma unroll
        for (int i = 0; i < 5; i++) {
            float x = (float)(i - 2);
            sp[i] = __expf(-x*x * 0.02f);
            float g = __expf(-2.f * x*x);
            g2[i] = g; s += g;
        }
        float inv = 1.f / s;
#pragma unroll
        for (int i = 0; i < 5; i++) g2[i] *= inv;
    }

    int ry = ty + 2, rx = tx + 2;
    float cr = sg[0][ry][rx], cg = sg[1][ry][rx], cb = sg[2][ry][rx], ce = sg[3][ry][rx];

    float wr[NTAP], we[NTAP];
    float sr = 0.f, se = 0.f;
#pragma unroll
    for (int dy = 0; dy < 5; dy++) {
#pragma unroll
        for (int dx = 0; dx < 5; dx++) {
            int t = dy*5 + dx;
            float d = fabsf(sg[0][ry+dy-2][rx+dx-2] - cr)
                    + fabsf(sg[1][ry+dy-2][rx+dx-2] - cg)
                    + fabsf(sg[2][ry+dy-2][rx+dx-2] - cb);
            float s2 = sp[dy] * sp[dx];
            float w  = s2 * __expf(-2.f * d * d);
            wr[t] = w; sr += w;
            float de = fabsf(sg[3][ry+dy-2][rx+dx-2] - ce);
            float w2 = s2 * __expf(-2.f * de * de);
            we[t] = w2; se += w2;
        }
    }
    float isr = 1.f / sr, ise = 1.f / se;
    int pix = b*HW + (y0 + ty)*W + (x0 + tx);
#pragma unroll
    for (int dy = 0; dy < 5; dy++) {
#pragma unroll
        for (int dx = 0; dx < 5; dx++) {
            int t = dy*5 + dx;
            g_wc[t*(NB*HW) + pix] = g2[dy]*g2[dx] + wr[t]*isr + we[t]*ise;
        }
    }
}

// ---------------------------------------------------------------------------
// Kernel 3: one CRF iteration, pair-planar.
// Tile 64x8, block (32,8)=256 thr, 2 px/thread, 3 CTAs/SM.
// smem [row 12][cc 11][px 68][2] fp32; LDS.128 yields two aligned FFMA2
// operands (no packs). Fill: 1 thread per (row,cc) plane, 34x 16B cp.async.
// ---------------------------------------------------------------------------
#define TX 64
#define TY 8
#define SWPX 68          // px cols x0-2 .. x0+65
#define SH 12
#define PLB 544          // bytes per (row,cc) plane = 68*8
#define RPB (NCC*PLB)    // 5984 bytes per row

template<bool FINAL>
__global__ void __launch_bounds__(256, 3) crf_iter(const float* __restrict__ unary,
                                                   const float* __restrict__ qin,
                                                   float* __restrict__ qout,
                                                   float* __restrict__ outp) {
    __shared__ float sq[SH*NCC*SWPX*2];   // 71808 B
    int tx = threadIdx.x, ty = threadIdx.y;
    int b = blockIdx.z;
    int x0 = blockIdx.x * TX, y0 = blockIdx.y * TY;
    int tid = ty * 32 + tx;
    int lastbx = (int)gridDim.x - 1;

    const float* qb = qin + (size_t)b * H * NCC * (W*2);
    uint32_t sbase = (uint32_t)__cvta_generic_to_shared(sq);

    // ---- fill: one thread per (row, cc) plane ----
    if (tid < SH*NCC) {
        int row = tid / NCC, cc = tid % NCC;
        int gy = reflect_idx(y0 + row - 2, H);
        const float* pl = qb + ((size_t)gy*NCC + cc)*(W*2);
        const float* src = pl + (x0 - 2)*2;          // chunk ch covers px x0-2+2ch
        uint32_t dst = sbase + (uint32_t)(row*RPB + cc*PLB);
        int chlo = (blockIdx.x == 0) ? 1 : 0;
        int chhi = (blockIdx.x == lastbx) ? 33 : 34;
        for (int ch = chlo; ch < chhi; ch++) {
            asm volatile("cp.async.cg.shared.global [%0], [%1], 16;"
                         :: "r"(dst + ch*16), "l"(src + ch*4));
        }
        if (blockIdx.x == 0) {
            // local px 0,1 -> x=-2,-1 -> gx=2,1
            float2 v0 = *reinterpret_cast<const float2*>(pl + 2*2);
            float2 v1 = *reinterpret_cast<const float2*>(pl + 1*2);
            *reinterpret_cast<float2*>(reinterpret_cast<char*>(sq) + row*RPB + cc*PLB)     = v0;
            *reinterpret_cast<float2*>(reinterpret_cast<char*>(sq) + row*RPB + cc*PLB + 8) = v1;
        }
        if (blockIdx.x == lastbx) {
            // local px 66,67 -> x=512,513 -> gx=510,509
            float2 v0 = *reinterpret_cast<const float2*>(pl + 510*2);
            float2 v1 = *reinterpret_cast<const float2*>(pl + 509*2);
            *reinterpret_cast<float2*>(reinterpret_cast<char*>(sq) + row*RPB + cc*PLB + 66*8) = v0;
            *reinterpret_cast<float2*>(reinterpret_cast<char*>(sq) + row*RPB + cc*PLB + 67*8) = v1;
        }
    }
    asm volatile("cp.async.commit_group;");
    asm volatile("cp.async.wait_group 0;" ::: "memory");
    __syncthreads();

    int px0 = x0 + 2*tx;
    int gy  = y0 + ty;

    unsigned long long acc0[NCC], acc1[NCC];
#pragma unroll
    for (int cc = 0; cc < NCC; cc++) { acc0[cc] = 0ULL; acc1[cc] = 0ULL; }

    int wbase = b*HW + gy*W + px0;
    const char* sb = reinterpret_cast<const char*>(sq);

#pragma unroll
    for (int dy = 0; dy < 5; dy++) {
        const float* wp = g_wc + (size_t)(dy*5)*NBHW + wbase;
        float2 c0 = *reinterpret_cast<const float2*>(wp);
        float2 c1 = *reinterpret_cast<const float2*>(wp +   (size_t)NBHW);
        float2 c2 = *reinterpret_cast<const float2*>(wp + 2*(size_t)NBHW);
        float2 c3 = *reinterpret_cast<const float2*>(wp + 3*(size_t)NBHW);
        float2 c4 = *reinterpret_cast<const float2*>(wp + 4*(size_t)NBHW);
        unsigned long long CC00 = pk2(c0.x, c0.x), CC10 = pk2(c0.y, c0.y);
        unsigned long long CC01 = pk2(c1.x, c1.x), CC11 = pk2(c1.y, c1.y);
        unsigned long long CC02 = pk2(c2.x, c2.x), CC12 = pk2(c2.y, c2.y);
        unsigned long long CC03 = pk2(c3.x, c3.x), CC13 = pk2(c3.y, c3.y);
        unsigned long long CC04 = pk2(c4.x, c4.x), CC14 = pk2(c4.y, c4.y);

        const char* rb = sb + (ty + dy)*RPB + tx*16;   // window cols 2tx..2tx+5
#pragma unroll
        for (int cc = 0; cc < NCC; cc++) {
            const char* a = rb + cc*PLB;
            ulonglong2 w01 = *reinterpret_cast<const ulonglong2*>(a);       // cols 0,1
            ulonglong2 w23 = *reinterpret_cast<const ulonglong2*>(a + 16);  // cols 2,3
            ulonglong2 w45 = *reinterpret_cast<const ulonglong2*>(a + 32);  // cols 4,5
            FMA2(acc0[cc], CC00, w01.x);
            FMA2(acc0[cc], CC01, w01.y);
            FMA2(acc0[cc], CC02, w23.x);
            FMA2(acc0[cc], CC03, w23.y);
            FMA2(acc0[cc], CC04, w45.x);
            FMA2(acc1[cc], CC10, w01.y);
            FMA2(acc1[cc], CC11, w23.x);
            FMA2(acc1[cc], CC12, w23.y);
            FMA2(acc1[cc], CC13, w45.x);
            FMA2(acc1[cc], CC14, w45.y);
        }
    }

    // ---- epilogue: q = softmax(unary - F) ----
    const float* ub = unary + (size_t)b * NC * HW + gy*W + px0;
    float s0 = 0.f, s1 = 0.f;
#pragma unroll
    for (int cc = 0; cc < NCC; cc++) {
        float fa, fb, ga, gb;
        upk2(fa, fb, acc0[cc]);   // px0: ch 2cc, 2cc+1
        upk2(ga, gb, acc1[cc]);   // px1
        float2 uA = *reinterpret_cast<const float2*>(ub + (size_t)(2*cc)*HW);
        float e00 = __expf(uA.x - fa);
        float e10 = __expf(uA.y - ga);
        float e01 = 0.f, e11 = 0.f;
        if (cc < 10) {
            float2 uB = *reinterpret_cast<const float2*>(ub + (size_t)(2*cc+1)*HW);
            e01 = __expf(uB.x - fb);
            e11 = __expf(uB.y - gb);
        }
        acc0[cc] = pk2(e00, e01);
        acc1[cc] = pk2(e10, e11);
        s0 += e00 + e01;
        s1 += e10 + e11;
    }
    float i0 = 1.f / s0, i1 = 1.f / s1;

    if (FINAL) {
        float* op = outp + (size_t)b * NC * HW + gy*W + px0;
#pragma unroll
        for (int cc = 0; cc < NCC; cc++) {
            float e00, e01, e10, e11;
            upk2(e00, e01, acc0[cc]);
            upk2(e10, e11, acc1[cc]);
            float2 vA; vA.x = e00*i0; vA.y = e10*i1;
            *reinterpret_cast<float2*>(op + (size_t)(2*cc)*HW) = vA;
            if (cc < 10) {
                float2 vB; vB.x = e01*i0; vB.y = e11*i1;
                *reinterpret_cast<float2*>(op + (size_t)(2*cc+1)*HW) = vB;
            }
        }
    } else {
        unsigned long long I0 = pk2(i0, i0), I1 = pk2(i1, i1);
        float* qo = qout + (size_t)b * H * NCC * (W*2)
                         + ((size_t)gy*NCC)*(W*2) + px0*2;
#pragma unroll
        for (int cc = 0; cc < NCC; cc++) {
            ulonglong2 st;
            MUL2(st.x, acc0[cc], I0);   // px0 pair
            MUL2(st.y, acc1[cc], I1);   // px1 pair
            *reinterpret_cast<ulonglong2*>(qo + cc*(W*2)) = st;
        }
    }
}

// ---------------------------------------------------------------------------
extern "C" void kernel_launch(void* const* d_in, const int* in_sizes, int n_in,
                              void* d_out, int out_size) {
    const float *unary = nullptr, *image = nullptr, *edges = nullptr;
    for (int i = 0; i < n_in; i++) {
        if      (in_sizes[i] == NB*NC*HW) unary = (const float*)d_in[i];
        else if (in_sizes[i] == NB*3*HW)  image = (const float*)d_in[i];
        else if (in_sizes[i] == NB*HW)    edges = (const float*)d_in[i];
    }
    float* out = (float*)d_out;

    float *qA = nullptr, *qB = nullptr;
    cudaGetSymbolAddress((void**)&qA, g_qA);
    cudaGetSymbolAddress((void**)&qB, g_qB);

    init_softmax<<<(NPIX + 255)/256, 256>>>(unary, qA);
    compute_weights<<<dim3(W/32, H/8, NB), dim3(32, 8)>>>(image, edges);

    dim3 gi(W/TX, H/TY, NB), bi(32, 8);
    const float* cur = qA;
    for (int it = 0; it < 9; it++) {
        float* dst = (cur == qA) ? qB : qA;
        crf_iter<false><<<gi, bi>>>(unary, cur, dst, nullptr);
        cur = dst;
    }
    crf_iter<true><<<gi, bi>>>(unary, cur, nullptr, out);
}

// round 12
// speedup vs baseline: 1.7891x; 1.0905x over previous
#include <cuda_runtime.h>
#include <cuda_fp16.h>
#include <cstdint>

#define H 512
#define W 512
#define HW (H*W)
#define NB 2
#define NC 21
#define NCC 11           // channel pairs (ch20 paired with zero pad)
#define NPIX (NB*HW)
#define NTAP 25
#define NBHW (NB*HW)

// q buffers: pair-planar layout [b][y][cc][x][2] fp32; coefs planar fp16
__device__ float  g_qA[(size_t)NB*H*NCC*W*2];
__device__ float  g_qB[(size_t)NB*H*NCC*W*2];
__device__ __half g_wch[NTAP*NB*HW];

__device__ __forceinline__ int reflect_idx(int i, int n) {
    if (i < 0) i = -i;
    if (i >= n) i = 2*n - 2 - i;
    return i;
}

__device__ __forceinline__ unsigned long long pk2(float lo, float hi) {
    unsigned long long r;
    asm("mov.b64 %0, {%1, %2};" : "=l"(r) : "f"(lo), "f"(hi));
    return r;
}
__device__ __forceinline__ void upk2(float& lo, float& hi, unsigned long long v) {
    asm("mov.b64 {%0, %1}, %2;" : "=f"(lo), "=f"(hi) : "l"(v));
}
#define FMA2(acc, a, b) \
    asm("fma.rn.f32x2 %0, %1, %2, %0;" : "+l"(acc) : "l"(a), "l"(b))
#define MUL2(out, a, b) \
    asm("mul.rn.f32x2 %0, %1, %2;" : "=l"(out) : "l"(a), "l"(b))

// ---------------------------------------------------------------------------
// Kernel 1: q0 = softmax(unary), written pair-planar
// ---------------------------------------------------------------------------
__global__ void __launch_bounds__(256) init_softmax(const float* __restrict__ unary,
                                                    float* __restrict__ q) {
    int idx = blockIdx.x * 256 + threadIdx.x;
    if (idx >= NPIX) return;
    int b = idx / HW, pix = idx % HW;
    int y = pix / W, x = pix % W;
    const float* u = unary + (size_t)b * NC * HW + pix;
    float e[NC];
    float s = 0.f;
#pragma unroll
    for (int c = 0; c < NC; c++) { e[c] = __expf(u[c*HW]); s += e[c]; }
    float inv = 1.f / s;
    float* qr = q + ((size_t)(b*H + y)*NCC)*(W*2) + x*2;
#pragma unroll
    for (int cc = 0; cc < 10; cc++) {
        float2 v; v.x = e[2*cc]*inv; v.y = e[2*cc+1]*inv;
        *reinterpret_cast<float2*>(qr + cc*(W*2)) = v;
    }
    float2 v10; v10.x = e[20]*inv; v10.y = 0.f;
    *reinterpret_cast<float2*>(qr + 10*(W*2)) = v10;
}

// ---------------------------------------------------------------------------
// Kernel 2: combined coefficients (fp16, planar SoA [tap][b][y][x])
// ---------------------------------------------------------------------------
__global__ void __launch_bounds__(256) compute_weights(const float* __restrict__ image,
                                                       const float* __restrict__ edges) {
    __shared__ float sg[4][12][36];
    int tx = threadIdx.x, ty = threadIdx.y;
    int b = blockIdx.z;
    int x0 = blockIdx.x * 32, y0 = blockIdx.y * 8;
    int tid = ty * 32 + tx;

    for (int idx = tid; idx < 4*12*36; idx += 256) {
        int ch = idx / (12*36);
        int r  = idx % (12*36);
        int ry = r / 36, sx = r % 36;
        int gy = reflect_idx(y0 + ry - 2, H);
        int gx = reflect_idx(x0 + sx - 2, W);
        float v;
        if (ch < 3) v = image[((size_t)(b*3 + ch))*HW + gy*W + gx];
        else        v = edges[(size_t)b*HW + gy*W + gx];
        sg[ch][ry][sx] = v;
    }
    __syncthreads();

    float sp[5], g2[5];
    {
        float s = 0.f;
#pragma unroll
        for (int i = 0; i < 5; i++) {
            float x = (float)(i - 2);
            sp[i] = __expf(-x*x * 0.02f);
            float g = __expf(-2.f * x*x);
            g2[i] = g; s += g;
        }
        float inv = 1.f / s;
#pragma unroll
        for (int i = 0; i < 5; i++) g2[i] *= inv;
    }

    int ry = ty + 2, rx = tx + 2;
    float cr = sg[0][ry][rx], cg = sg[1][ry][rx], cb = sg[2][ry][rx], ce = sg[3][ry][rx];

    float wr[NTAP], we[NTAP];
    float sr = 0.f, se = 0.f;
#pragma unroll
    for (int dy = 0; dy < 5; dy++) {
#pragma unroll
        for (int dx = 0; dx < 5; dx++) {
            int t = dy*5 + dx;
            float d = fabsf(sg[0][ry+dy-2][rx+dx-2] - cr)
                    + fabsf(sg[1][ry+dy-2][rx+dx-2] - cg)
                    + fabsf(sg[2][ry+dy-2][rx+dx-2] - cb);
            float s2 = sp[dy] * sp[dx];
            float w  = s2 * __expf(-2.f * d * d);
            wr[t] = w; sr += w;
            float de = fabsf(sg[3][ry+dy-2][rx+dx-2] - ce);
            float w2 = s2 * __expf(-2.f * de * de);
            we[t] = w2; se += w2;
        }
    }
    float isr = 1.f / sr, ise = 1.f / se;
    int pix = b*HW + (y0 + ty)*W + (x0 + tx);
#pragma unroll
    for (int dy = 0; dy < 5; dy++) {
#pragma unroll
        for (int dx = 0; dx < 5; dx++) {
            int t = dy*5 + dx;
            g_wch[t*(NB*HW) + pix] = __float2half(g2[dy]*g2[dx] + wr[t]*isr + we[t]*ise);
        }
    }
}

// ---------------------------------------------------------------------------
// Kernel 3: one CRF iteration, pair-planar.
// Tile 64x8, block (32,8)=256 thr, 2 px/thread, 3 CTAs/SM.
// smem [row 12][cc 11][px 68][2] fp32; LDS.128 yields two aligned FFMA2
// operands (no packs). Fill: ALL 256 threads share the 4488 16B cp.async
// chunks (18/thread). Coefs fp16 (half the DRAM traffic).
// ---------------------------------------------------------------------------
#define TX 64
#define TY 8
#define SWPX 68          // px cols x0-2 .. x0+65
#define SH 12
#define PLB 544          // bytes per (row,cc) plane = 68*8
#define RPB (NCC*PLB)    // 5984 bytes per row
#define NCHK (SH*NCC*34) // 4488 16B chunks

template<bool FINAL>
__global__ void __launch_bounds__(256, 3) crf_iter(const float* __restrict__ unary,
                                                   const float* __restrict__ qin,
                                                   float* __restrict__ qout,
                                                   float* __restrict__ outp) {
    __shared__ float sq[SH*NCC*SWPX*2];   // 71808 B
    int tx = threadIdx.x, ty = threadIdx.y;
    int b = blockIdx.z;
    int x0 = blockIdx.x * TX, y0 = blockIdx.y * TY;
    int tid = ty * 32 + tx;
    int lastbx = (int)gridDim.x - 1;
    bool bx0 = (blockIdx.x == 0), bxL = (blockIdx.x == lastbx);

    const float* qb = qin + (size_t)b * H * NCC * (W*2);
    uint32_t sbase = (uint32_t)__cvta_generic_to_shared(sq);

    // ---- fill: all 256 threads, chunk idx = (row, cc, cx), incremental ----
    {
        int idx = tid;
        int cx  = tid % 34;
        int pl  = tid / 34;
        int cc  = pl % NCC;
        int row = pl / NCC;
#pragma unroll
        for (int it = 0; it < 18; it++) {
            if (idx < NCHK) {
                bool skip = (bx0 && cx == 0) || (bxL && cx == 33);
                if (!skip) {
                    int gy = reflect_idx(y0 + row - 2, H);
                    const float* src = qb + ((size_t)gy*NCC + cc)*(W*2)
                                     + (x0 - 2)*2 + cx*4;
                    uint32_t dst = sbase + (uint32_t)(row*RPB + cc*PLB + cx*16);
                    asm volatile("cp.async.cg.shared.global [%0], [%1], 16;"
                                 :: "r"(dst), "l"(src));
                }
            }
            idx += 256;
            cx += 18; int cinc = 7;
            if (cx >= 34) { cx -= 34; cinc = 8; }
            cc += cinc;
            if (cc >= NCC) { cc -= NCC; row++; }
        }
        asm volatile("cp.async.commit_group;");
    }
    // boundary reflect fix-ups (plain STS, one thread per (row,cc) plane)
    if ((bx0 || bxL) && tid < SH*NCC) {
        int row = tid / NCC, cc = tid % NCC;
        int gy = reflect_idx(y0 + row - 2, H);
        const float* pl = qb + ((size_t)gy*NCC + cc)*(W*2);
        char* base = reinterpret_cast<char*>(sq) + row*RPB + cc*PLB;
        if (bx0) {
            float2 v0 = *reinterpret_cast<const float2*>(pl + 2*2);   // x=-2 -> gx=2
            float2 v1 = *reinterpret_cast<const float2*>(pl + 1*2);   // x=-1 -> gx=1
            *reinterpret_cast<float2*>(base)     = v0;
            *reinterpret_cast<float2*>(base + 8) = v1;
        }
        if (bxL) {
            float2 v0 = *reinterpret_cast<const float2*>(pl + 510*2); // x=512 -> 510
            float2 v1 = *reinterpret_cast<const float2*>(pl + 509*2); // x=513 -> 509
            *reinterpret_cast<float2*>(base + 66*8) = v0;
            *reinterpret_cast<float2*>(base + 67*8) = v1;
        }
    }
    asm volatile("cp.async.wait_group 0;" ::: "memory");
    __syncthreads();

    int px0 = x0 + 2*tx;
    int gy  = y0 + ty;

    unsigned long long acc0[NCC], acc1[NCC];
#pragma unroll
    for (int cc = 0; cc < NCC; cc++) { acc0[cc] = 0ULL; acc1[cc] = 0ULL; }

    int wbase = b*HW + gy*W + px0;
    const char* sb = reinterpret_cast<const char*>(sq);

#pragma unroll
    for (int dy = 0; dy < 5; dy++) {
        const __half* wp = g_wch + (size_t)(dy*5)*NBHW + wbase;
        float2 c0 = __half22float2(*reinterpret_cast<const __half2*>(wp));
        float2 c1 = __half22float2(*reinterpret_cast<const __half2*>(wp +   (size_t)NBHW));
        float2 c2 = __half22float2(*reinterpret_cast<const __half2*>(wp + 2*(size_t)NBHW));
        float2 c3 = __half22float2(*reinterpret_cast<const __half2*>(wp + 3*(size_t)NBHW));
        float2 c4 = __half22float2(*reinterpret_cast<const __half2*>(wp + 4*(size_t)NBHW));
        unsigned long long CC00 = pk2(c0.x, c0.x), CC10 = pk2(c0.y, c0.y);
        unsigned long long CC01 = pk2(c1.x, c1.x), CC11 = pk2(c1.y, c1.y);
        unsigned long long CC02 = pk2(c2.x, c2.x), CC12 = pk2(c2.y, c2.y);
        unsigned long long CC03 = pk2(c3.x, c3.x), CC13 = pk2(c3.y, c3.y);
        unsigned long long CC04 = pk2(c4.x, c4.x), CC14 = pk2(c4.y, c4.y);

        const char* rb = sb + (ty + dy)*RPB + tx*16;   // window cols 2tx..2tx+5
#pragma unroll
        for (int cc = 0; cc < NCC; cc++) {
            const char* a = rb + cc*PLB;
            ulonglong2 w01 = *reinterpret_cast<const ulonglong2*>(a);       // cols 0,1
            ulonglong2 w23 = *reinterpret_cast<const ulonglong2*>(a + 16);  // cols 2,3
            ulonglong2 w45 = *reinterpret_cast<const ulonglong2*>(a + 32);  // cols 4,5
            FMA2(acc0[cc], CC00, w01.x);
            FMA2(acc0[cc], CC01, w01.y);
            FMA2(acc0[cc], CC02, w23.x);
            FMA2(acc0[cc], CC03, w23.y);
            FMA2(acc0[cc], CC04, w45.x);
            FMA2(acc1[cc], CC10, w01.y);
            FMA2(acc1[cc], CC11, w23.x);
            FMA2(acc1[cc], CC12, w23.y);
            FMA2(acc1[cc], CC13, w45.x);
            FMA2(acc1[cc], CC14, w45.y);
        }
    }

    // ---- epilogue: q = softmax(unary - F) ----
    const float* ub = unary + (size_t)b * NC * HW + gy*W + px0;
    float s0 = 0.f, s1 = 0.f;
#pragma unroll
    for (int cc = 0; cc < NCC; cc++) {
        float fa, fb, ga, gb;
        upk2(fa, fb, acc0[cc]);   // px0: ch 2cc, 2cc+1
        upk2(ga, gb, acc1[cc]);   // px1
        float2 uA = *reinterpret_cast<const float2*>(ub + (size_t)(2*cc)*HW);
        float e00 = __expf(uA.x - fa);
        float e10 = __expf(uA.y - ga);
        float e01 = 0.f, e11 = 0.f;
        if (cc < 10) {
            float2 uB = *reinterpret_cast<const float2*>(ub + (size_t)(2*cc+1)*HW);
            e01 = __expf(uB.x - fb);
            e11 = __expf(uB.y - gb);
        }
        acc0[cc] = pk2(e00, e01);
        acc1[cc] = pk2(e10, e11);
        s0 += e00 + e01;
        s1 += e10 + e11;
    }
    float i0 = 1.f / s0, i1 = 1.f / s1;

    if (FINAL) {
        float* op = outp + (size_t)b * NC * HW + gy*W + px0;
#pragma unroll
        for (int cc = 0; cc < NCC; cc++) {
            float e00, e01, e10, e11;
            upk2(e00, e01, acc0[cc]);
            upk2(e10, e11, acc1[cc]);
            float2 vA; vA.x = e00*i0; vA.y = e10*i1;
            *reinterpret_cast<float2*>(op + (size_t)(2*cc)*HW) = vA;
            if (cc < 10) {
                float2 vB; vB.x = e01*i0; vB.y = e11*i1;
                *reinterpret_cast<float2*>(op + (size_t)(2*cc+1)*HW) = vB;
            }
        }
    } else {
        unsigned long long I0 = pk2(i0, i0), I1 = pk2(i1, i1);
        float* qo = qout + (size_t)b * H * NCC * (W*2)
                         + ((size_t)gy*NCC)*(W*2) + px0*2;
#pragma unroll
        for (int cc = 0; cc < NCC; cc++) {
            ulonglong2 st;
            MUL2(st.x, acc0[cc], I0);   // px0 pair
            MUL2(st.y, acc1[cc], I1);   // px1 pair
            *reinterpret_cast<ulonglong2*>(qo + cc*(W*2)) = st;
        }
    }
}

// ---------------------------------------------------------------------------
extern "C" void kernel_launch(void* const* d_in, const int* in_sizes, int n_in,
                              void* d_out, int out_size) {
    const float *unary = nullptr, *image = nullptr, *edges = nullptr;
    for (int i = 0; i < n_in; i++) {
        if      (in_sizes[i] == NB*NC*HW) unary = (const float*)d_in[i];
        else if (in_sizes[i] == NB*3*HW)  image = (const float*)d_in[i];
        else if (in_sizes[i] == NB*HW)    edges = (const float*)d_in[i];
    }
    float* out = (float*)d_out;

    float *qA = nullptr, *qB = nullptr;
    cudaGetSymbolAddress((void**)&qA, g_qA);
    cudaGetSymbolAddress((void**)&qB, g_qB);

    init_softmax<<<(NPIX + 255)/256, 256>>>(unary, qA);
    compute_weights<<<dim3(W/32, H/8, NB), dim3(32, 8)>>>(image, edges);

    dim3 gi(W/TX, H/TY, NB), bi(32, 8);
    const float* cur = qA;
    for (int it = 0; it < 9; it++) {
        float* dst = (cur == qA) ? qB : qA;
        crf_iter<false><<<gi, bi>>>(unary, cur, dst, nullptr);
        cur = dst;
    }
    crf_iter<true><<<gi, bi>>>(unary, cur, nullptr, out);
}